// round 11
// baseline (speedup 1.0000x reference)
#include <cuda_runtime.h>
#include <math.h>
#include <stdint.h>

#define BATCH 2
#define NQ 2048
#define NKV 2112
#define CDIM 1024
#define NH 16
#define HD 64
#define NKEEP 2048
#define QW 64
#define SCALE 0.125f

// Scratch (device globals; allocation is forbidden)
__device__ float g_Qh[BATCH * NH * NQ * HD];
__device__ float g_Kh[BATCH * NH * NKV * HD];
__device__ float g_Vh[BATCH * NH * NKV * HD];
__device__ float g_AO[BATCH * NQ * CDIM];
__device__ float g_ct[NQ * 32];
__device__ float g_st[NQ * 32];
// tf32-converted inputs
__device__ float g_qt[BATCH * NQ * CDIM];
__device__ float g_kt[BATCH * NKV * CDIM];
__device__ float g_vt[BATCH * NKV * CDIM];
__device__ float g_Wqt[CDIM * CDIM];
__device__ float g_Wkt[CDIM * CDIM];
__device__ float g_Wvt[CDIM * CDIM];
__device__ float g_Wot[CDIM * CDIM];

// ---------------------------------------------------------------------------
__device__ __forceinline__ float f2tf(float f) {
    uint32_t u;
    asm("cvt.rna.tf32.f32 %0, %1;" : "=r"(u) : "f"(f));
    return __uint_as_float(u);
}
__device__ __forceinline__ float4 f2tf4(float4 v) {
    return make_float4(f2tf(v.x), f2tf(v.y), f2tf(v.z), f2tf(v.w));
}

__device__ __forceinline__ void mma8(float c[4], float a0, float a1, float a2, float a3,
                                     float b0, float b1) {
    asm volatile(
        "mma.sync.aligned.m16n8k8.row.col.f32.tf32.tf32.f32 "
        "{%0,%1,%2,%3}, {%4,%5,%6,%7}, {%8,%9}, {%0,%1,%2,%3};\n"
        : "+f"(c[0]), "+f"(c[1]), "+f"(c[2]), "+f"(c[3])
        : "r"(__float_as_uint(a0)), "r"(__float_as_uint(a1)),
          "r"(__float_as_uint(a2)), "r"(__float_as_uint(a3)),
          "r"(__float_as_uint(b0)), "r"(__float_as_uint(b1)));
}

__device__ __forceinline__ void cp16(void* smem_dst, const void* gmem_src) {
    uint32_t s = (uint32_t)__cvta_generic_to_shared(smem_dst);
    asm volatile("cp.async.cg.shared.global [%0], [%1], 16;\n" :: "r"(s), "l"(gmem_src));
}
__device__ __forceinline__ void cp_commit() {
    asm volatile("cp.async.commit_group;\n");
}
template <int N>
__device__ __forceinline__ void cp_wait() {
    asm volatile("cp.async.wait_group %0;\n" :: "n"(N));
}

// ---------------------------------------------------------------------------
// tf32 pre-conversion of all GEMM operands (grid-stride, z = tensor id)
// ---------------------------------------------------------------------------
struct CvtJobs {
    const float4* src[7];
    float4* dst[7];
    int n4[7];
};

__global__ void cvt_tf32_kernel(CvtJobs jobs) {
    int z = blockIdx.z;
    const float4* s = jobs.src[z];
    float4* d = jobs.dst[z];
    int n4 = jobs.n4[z];
    int stride = gridDim.x * blockDim.x;
    for (int i = blockIdx.x * blockDim.x + threadIdx.x; i < n4; i += stride)
        d[i] = f2tf4(s[i]);
}

// ---------------------------------------------------------------------------
__global__ void rope_table_kernel(float* __restrict__ ct, float* __restrict__ st) {
    int idx = blockIdx.x * blockDim.x + threadIdx.x;
    if (idx >= NQ * 32) return;
    int n = idx >> 5;
    int p = idx & 31;
    int j = p & 15;
    float coord = (p < 16) ? (float)(n & (QW - 1)) : (float)(n / QW);
    float freq = powf(10000.0f, -(float)j / 16.0f);
    float ang = coord * freq;
    ct[idx] = cosf(ang);
    st[idx] = sinf(ang);
}

// ---------------------------------------------------------------------------
// tf32 GEMM (inputs pre-converted): out = A(M x 1024) @ W(1024 x 1024) + bias
// Block 128x128, BK=16, 256 threads, 8 warps (4M x 2N), warp tile 32x64.
// 3-stage cp.async pipeline; 1 syncthreads per K-iter.
// mode: 0 V-scatter+tf32, 1 Q rope+scale+tf32, 2 K rope(n<NKEEP)+tf32, 3 plain f32.
// blockIdx.z selects job (merged Q/K/V launch).
// ---------------------------------------------------------------------------
#define BK 16
#define A_STR 20
#define B_STR 136
#define NK_IT 64
#define A_BUF (128 * A_STR)   // 2560 floats / stage
#define B_BUF (BK * B_STR)    // 2176 floats / stage
#define GEMM_SMEM ((3 * A_BUF + 3 * B_BUF) * 4)

struct GemmJob {
    const float* A;
    const float* W;
    const float* bias;
    float* out;
    int Ntok;
    int mode;
    int yblocks;
};
struct GemmJobs { GemmJob j[3]; };

__global__ __launch_bounds__(256, 2)
void gemm_tf32(GemmJobs jobs, const float* __restrict__ ct, const float* __restrict__ st) {
    const GemmJob jb = jobs.j[blockIdx.z];
    if ((int)blockIdx.y >= jb.yblocks) return;

    extern __shared__ float gsm[];
    float* As = gsm;                  // [3][128][A_STR]
    float* Bs = gsm + 3 * A_BUF;      // [3][BK][B_STR]

    int tid = threadIdx.x;
    int lane = tid & 31, wid = tid >> 5;
    int wm = wid >> 1, wn = wid & 1;
    int g = lane >> 2, q4 = lane & 3;
    int row0 = blockIdx.y * 128, col0 = blockIdx.x * 128;

    int ar = tid >> 1, ac = (tid & 1) << 3;
    int br = tid >> 4, bc = (tid & 15) << 3;

    const float* Ap = jb.A + (size_t)(row0 + ar) * 1024 + ac;
    const float* Wp = jb.W + (size_t)br * 1024 + col0 + bc;

    float acc[2][8][4];
#pragma unroll
    for (int mi = 0; mi < 2; mi++)
#pragma unroll
        for (int ni = 0; ni < 8; ni++)
#pragma unroll
            for (int j = 0; j < 4; j++) acc[mi][ni][j] = 0.0f;

    // prologue: issue k-blocks 0 and 1
#pragma unroll
    for (int kb = 0; kb < 2; kb++) {
        float* Ad = As + kb * A_BUF + ar * A_STR + ac;
        float* Bd = Bs + kb * B_BUF + br * B_STR + bc;
        cp16(Ad,     Ap + kb * BK);
        cp16(Ad + 4, Ap + kb * BK + 4);
        cp16(Bd,     Wp + (size_t)kb * BK * 1024);
        cp16(Bd + 4, Wp + (size_t)kb * BK * 1024 + 4);
        cp_commit();
    }

    for (int it = 0; it < NK_IT; it++) {
        cp_wait<1>();
        __syncthreads();

        // issue k-block it+2 (overwrites stage of it-1; barrier above makes it safe)
        int kb = it + 2;
        if (kb < NK_IT) {
            int s = kb % 3;
            float* Ad = As + s * A_BUF + ar * A_STR + ac;
            float* Bd = Bs + s * B_BUF + br * B_STR + bc;
            cp16(Ad,     Ap + kb * BK);
            cp16(Ad + 4, Ap + kb * BK + 4);
            cp16(Bd,     Wp + (size_t)kb * BK * 1024);
            cp16(Bd + 4, Wp + (size_t)kb * BK * 1024 + 4);
        }
        cp_commit();

        const float* Ac = As + (it % 3) * A_BUF;
        const float* Bc = Bs + (it % 3) * B_BUF;
#pragma unroll
        for (int kc = 0; kc < BK; kc += 8) {
            float a[2][4], b[8][2];
#pragma unroll
            for (int mi = 0; mi < 2; mi++) {
                int m = wm * 32 + mi * 16;
                a[mi][0] = Ac[(m + g) * A_STR + kc + q4];
                a[mi][1] = Ac[(m + 8 + g) * A_STR + kc + q4];
                a[mi][2] = Ac[(m + g) * A_STR + kc + 4 + q4];
                a[mi][3] = Ac[(m + 8 + g) * A_STR + kc + 4 + q4];
            }
#pragma unroll
            for (int ni = 0; ni < 8; ni++) {
                int n = wn * 64 + ni * 8 + g;
                b[ni][0] = Bc[(kc + q4) * B_STR + n];
                b[ni][1] = Bc[(kc + 4 + q4) * B_STR + n];
            }
#pragma unroll
            for (int mi = 0; mi < 2; mi++)
#pragma unroll
                for (int ni = 0; ni < 8; ni++)
                    mma8(acc[mi][ni], a[mi][0], a[mi][1], a[mi][2], a[mi][3],
                         b[ni][0], b[ni][1]);
        }
    }

    // epilogue
    int Ntok = jb.Ntok, mode = jb.mode;
#pragma unroll
    for (int mi = 0; mi < 2; mi++) {
#pragma unroll
        for (int ri = 0; ri < 2; ri++) {
            int gr = row0 + wm * 32 + mi * 16 + ri * 8 + g;
            int b = 0, n = gr;
            if (mode != 3) { b = gr / Ntok; n = gr - b * Ntok; }
            bool dorope = (mode == 1) || (mode == 2 && n < NKEEP);
#pragma unroll
            for (int ni = 0; ni < 8; ni++) {
                int gc = col0 + wn * 64 + ni * 8 + 2 * q4;
                float v0 = acc[mi][ni][ri * 2 + 0] + jb.bias[gc];
                float v1 = acc[mi][ni][ri * 2 + 1] + jb.bias[gc + 1];
                if (mode == 3) {
                    *(float2*)(jb.out + (size_t)gr * 1024 + gc) = make_float2(v0, v1);
                } else {
                    if (dorope) {
                        int p = (gc & 63) >> 1;
                        float cs = ct[n * 32 + p];
                        float sn = st[n * 32 + p];
                        float e = v0, o = v1;
                        v0 = e * cs - o * sn;
                        v1 = e * sn + o * cs;
                    }
                    if (mode == 1) { v0 *= SCALE; v1 *= SCALE; }
                    int h = (gc >> 6) & 15;
                    float* dst = jb.out + (((size_t)(b * NH + h) * Ntok + n) * HD + (gc & 63));
                    *(float2*)dst = make_float2(f2tf(v0), f2tf(v1));
                }
            }
        }
    }
}

// ---------------------------------------------------------------------------
// tf32 flash attention: block = one (b,h), 128 q rows; 8 warps x 16 rows.
// Bc=32, 2-stage cp.async K/V (inputs already tf32; Q already scaled).
// ---------------------------------------------------------------------------
#define QS_S 68
#define KS_S 68
#define VS_S 72
#define PS_S 36
#define BC 32
#define NTILE (NKV / BC)
#define FLASH_SMEM ((128 * QS_S + 2 * BC * KS_S + 2 * BC * VS_S + 128 * PS_S) * 4)

__global__ __launch_bounds__(256, 2)
void flash_tf32(const float* __restrict__ Qh, const float* __restrict__ Kh,
                const float* __restrict__ Vh, float* __restrict__ Out) {
    extern __shared__ float sm[];
    float* Qs = sm;                                    // [128][68]
    float* Ks0 = Qs + 128 * QS_S;                      // [2][32][68]
    float* Vs0 = Ks0 + 2 * BC * KS_S;                  // [2][32][72]
    float* Ps = Vs0 + 2 * BC * VS_S;                   // [128][36]

    int tid = threadIdx.x, lane = tid & 31, wid = tid >> 5;
    int g = lane >> 2, q4 = lane & 3;
    int bh = blockIdx.y, qt = blockIdx.x;
    int r0 = wid * 16;

    const float* Qb = Qh + ((size_t)bh * NQ + qt * 128) * HD;
    const float* Kb = Kh + (size_t)bh * NKV * HD;
    const float* Vb = Vh + (size_t)bh * NKV * HD;

    // staging coords: K/V tile = 32x64 floats = 512 float4, 2 per thread
    int sr[2], sdg[2];
#pragma unroll
    for (int t = 0; t < 2; t++) {
        int idx = tid + t * 256;
        sr[t] = idx >> 4;
        sdg[t] = (idx & 15) << 2;
    }

    // prologue: stage Q (8 cp16/thread) + K/V tile 0 (group 0)
#pragma unroll
    for (int t = 0; t < 8; t++) {
        int idx = tid + t * 256;
        int r = idx >> 4, dg = (idx & 15) << 2;
        cp16(&Qs[r * QS_S + dg], Qb + r * 64 + dg);
    }
#pragma unroll
    for (int t = 0; t < 2; t++) {
        cp16(&Ks0[sr[t] * KS_S + sdg[t]], Kb + sr[t] * 64 + sdg[t]);
        cp16(&Vs0[sr[t] * VS_S + sdg[t]], Vb + sr[t] * 64 + sdg[t]);
    }
    cp_commit();

    float m0 = -INFINITY, m1 = -INFINITY, l0 = 0.0f, l1 = 0.0f;
    float o[8][4];
#pragma unroll
    for (int ni = 0; ni < 8; ni++)
#pragma unroll
        for (int j = 0; j < 4; j++) o[ni][j] = 0.0f;

    for (int kt = 0; kt < NTILE; kt++) {
        __syncthreads();   // all threads done reading buffer (kt+1)&1 (tile kt-1)

        if (kt + 1 < NTILE) {
            int nxt = (kt + 1) & 1;
            const float* Kn = Kb + (size_t)(kt + 1) * BC * 64;
            const float* Vn = Vb + (size_t)(kt + 1) * BC * 64;
            float* Kd = Ks0 + nxt * BC * KS_S;
            float* Vd = Vs0 + nxt * BC * VS_S;
#pragma unroll
            for (int t = 0; t < 2; t++) {
                cp16(&Kd[sr[t] * KS_S + sdg[t]], Kn + sr[t] * 64 + sdg[t]);
                cp16(&Vd[sr[t] * VS_S + sdg[t]], Vn + sr[t] * 64 + sdg[t]);
            }
        }
        cp_commit();

        cp_wait<1>();      // tile kt (and Q on kt==0) resident
        __syncthreads();

        const float* Ksc = Ks0 + (kt & 1) * BC * KS_S;
        const float* Vsc = Vs0 + (kt & 1) * BC * VS_S;

        // S = Q @ K^T  (16 x 32 per warp)
        float s[4][4];
#pragma unroll
        for (int ni = 0; ni < 4; ni++)
#pragma unroll
            for (int j = 0; j < 4; j++) s[ni][j] = 0.0f;

#pragma unroll
        for (int kc = 0; kc < 64; kc += 8) {
            float a0 = Qs[(r0 + g) * QS_S + kc + q4];
            float a1 = Qs[(r0 + 8 + g) * QS_S + kc + q4];
            float a2 = Qs[(r0 + g) * QS_S + kc + 4 + q4];
            float a3 = Qs[(r0 + 8 + g) * QS_S + kc + 4 + q4];
#pragma unroll
            for (int ni = 0; ni < 4; ni++) {
                float b0 = Ksc[(ni * 8 + g) * KS_S + kc + q4];
                float b1 = Ksc[(ni * 8 + g) * KS_S + kc + 4 + q4];
                mma8(s[ni], a0, a1, a2, a3, b0, b1);
            }
        }

        // online softmax
        float mt0 = -INFINITY, mt1 = -INFINITY;
#pragma unroll
        for (int ni = 0; ni < 4; ni++) {
            mt0 = fmaxf(mt0, fmaxf(s[ni][0], s[ni][1]));
            mt1 = fmaxf(mt1, fmaxf(s[ni][2], s[ni][3]));
        }
        mt0 = fmaxf(mt0, __shfl_xor_sync(0xffffffffu, mt0, 1));
        mt0 = fmaxf(mt0, __shfl_xor_sync(0xffffffffu, mt0, 2));
        mt1 = fmaxf(mt1, __shfl_xor_sync(0xffffffffu, mt1, 1));
        mt1 = fmaxf(mt1, __shfl_xor_sync(0xffffffffu, mt1, 2));
        float mn0 = fmaxf(m0, mt0), mn1 = fmaxf(m1, mt1);
        float al0 = __expf(m0 - mn0), al1 = __expf(m1 - mn1);
        m0 = mn0; m1 = mn1;

        float sum0 = 0.0f, sum1 = 0.0f;
#pragma unroll
        for (int ni = 0; ni < 4; ni++) {
            s[ni][0] = __expf(s[ni][0] - mn0);
            s[ni][1] = __expf(s[ni][1] - mn0);
            s[ni][2] = __expf(s[ni][2] - mn1);
            s[ni][3] = __expf(s[ni][3] - mn1);
            sum0 += s[ni][0] + s[ni][1];
            sum1 += s[ni][2] + s[ni][3];
        }
        sum0 += __shfl_xor_sync(0xffffffffu, sum0, 1);
        sum0 += __shfl_xor_sync(0xffffffffu, sum0, 2);
        sum1 += __shfl_xor_sync(0xffffffffu, sum1, 1);
        sum1 += __shfl_xor_sync(0xffffffffu, sum1, 2);
        l0 = l0 * al0 + sum0;
        l1 = l1 * al1 + sum1;
#pragma unroll
        for (int ni = 0; ni < 8; ni++) {
            o[ni][0] *= al0; o[ni][1] *= al0;
            o[ni][2] *= al1; o[ni][3] *= al1;
        }

        // P (warp-private rows), tf32
#pragma unroll
        for (int ni = 0; ni < 4; ni++) {
            int c = ni * 8 + 2 * q4;
            *(float2*)&Ps[(r0 + g) * PS_S + c] =
                make_float2(f2tf(s[ni][0]), f2tf(s[ni][1]));
            *(float2*)&Ps[(r0 + 8 + g) * PS_S + c] =
                make_float2(f2tf(s[ni][2]), f2tf(s[ni][3]));
        }
        __syncwarp();

        // O += P @ V
#pragma unroll
        for (int kc = 0; kc < BC; kc += 8) {
            float a0 = Ps[(r0 + g) * PS_S + kc + q4];
            float a1 = Ps[(r0 + 8 + g) * PS_S + kc + q4];
            float a2 = Ps[(r0 + g) * PS_S + kc + 4 + q4];
            float a3 = Ps[(r0 + 8 + g) * PS_S + kc + 4 + q4];
#pragma unroll
            for (int ni = 0; ni < 8; ni++) {
                float b0 = Vsc[(kc + q4) * VS_S + ni * 8 + g];
                float b1 = Vsc[(kc + 4 + q4) * VS_S + ni * 8 + g];
                mma8(o[ni], a0, a1, a2, a3, b0, b1);
            }
        }
    }

    // epilogue: write tf32-rounded AO in (B, Nq, C) layout
    float inv0 = 1.0f / l0, inv1 = 1.0f / l1;
    int b = bh >> 4, h = bh & 15;
    int nr = qt * 128 + r0 + g;
    size_t base0 = ((size_t)(b * NQ + nr)) * CDIM + h * 64;
    size_t base1 = base0 + (size_t)8 * CDIM;
#pragma unroll
    for (int ni = 0; ni < 8; ni++) {
        int c = ni * 8 + 2 * q4;
        *(float2*)(Out + base0 + c) =
            make_float2(f2tf(o[ni][0] * inv0), f2tf(o[ni][1] * inv0));
        *(float2*)(Out + base1 + c) =
            make_float2(f2tf(o[ni][2] * inv1), f2tf(o[ni][3] * inv1));
    }
}

// ---------------------------------------------------------------------------
extern "C" void kernel_launch(void* const* d_in, const int* in_sizes, int n_in,
                              void* d_out, int out_size) {
    const float* q  = (const float*)d_in[0];
    const float* k  = (const float*)d_in[1];
    const float* v  = (const float*)d_in[2];
    const float* Wq = (const float*)d_in[3];
    const float* bq = (const float*)d_in[4];
    const float* Wk = (const float*)d_in[5];
    const float* bk = (const float*)d_in[6];
    const float* Wv = (const float*)d_in[7];
    const float* bv = (const float*)d_in[8];
    const float* Wo = (const float*)d_in[9];
    const float* bo = (const float*)d_in[10];
    float* out = (float*)d_out;

    float *pQ, *pK, *pV, *pAO, *pc, *ps;
    float *pqt, *pkt, *pvt, *pWq, *pWk, *pWv, *pWo;
    cudaGetSymbolAddress((void**)&pQ,  g_Qh);
    cudaGetSymbolAddress((void**)&pK,  g_Kh);
    cudaGetSymbolAddress((void**)&pV,  g_Vh);
    cudaGetSymbolAddress((void**)&pAO, g_AO);
    cudaGetSymbolAddress((void**)&pc,  g_ct);
    cudaGetSymbolAddress((void**)&ps,  g_st);
    cudaGetSymbolAddress((void**)&pqt, g_qt);
    cudaGetSymbolAddress((void**)&pkt, g_kt);
    cudaGetSymbolAddress((void**)&pvt, g_vt);
    cudaGetSymbolAddress((void**)&pWq, g_Wqt);
    cudaGetSymbolAddress((void**)&pWk, g_Wkt);
    cudaGetSymbolAddress((void**)&pWv, g_Wvt);
    cudaGetSymbolAddress((void**)&pWo, g_Wot);

    cudaFuncSetAttribute(gemm_tf32, cudaFuncAttributeMaxDynamicSharedMemorySize,
                         GEMM_SMEM);
    cudaFuncSetAttribute(flash_tf32, cudaFuncAttributeMaxDynamicSharedMemorySize,
                         FLASH_SMEM);

    // 1) pre-convert operands to tf32
    CvtJobs cj;
    cj.src[0] = (const float4*)q;  cj.dst[0] = (float4*)pqt; cj.n4[0] = BATCH * NQ  * CDIM / 4;
    cj.src[1] = (const float4*)k;  cj.dst[1] = (float4*)pkt; cj.n4[1] = BATCH * NKV * CDIM / 4;
    cj.src[2] = (const float4*)v;  cj.dst[2] = (float4*)pvt; cj.n4[2] = BATCH * NKV * CDIM / 4;
    cj.src[3] = (const float4*)Wq; cj.dst[3] = (float4*)pWq; cj.n4[3] = CDIM * CDIM / 4;
    cj.src[4] = (const float4*)Wk; cj.dst[4] = (float4*)pWk; cj.n4[4] = CDIM * CDIM / 4;
    cj.src[5] = (const float4*)Wv; cj.dst[5] = (float4*)pWv; cj.n4[5] = CDIM * CDIM / 4;
    cj.src[6] = (const float4*)Wo; cj.dst[6] = (float4*)pWo; cj.n4[6] = CDIM * CDIM / 4;
    cvt_tf32_kernel<<<dim3(528, 1, 7), 256>>>(cj);

    rope_table_kernel<<<(NQ * 32 + 255) / 256, 256>>>(pc, ps);

    // 2) merged Q/K/V projection GEMMs (z = job)
    GemmJobs pj;
    pj.j[0] = { pqt, pWq, bq, pQ, NQ,  1, (BATCH * NQ)  / 128 };  // 32
    pj.j[1] = { pkt, pWk, bk, pK, NKV, 2, (BATCH * NKV) / 128 };  // 33
    pj.j[2] = { pvt, pWv, bv, pV, NKV, 0, (BATCH * NKV) / 128 };  // 33
    gemm_tf32<<<dim3(8, 33, 3), 256, GEMM_SMEM>>>(pj, pc, ps);

    // 3) attention
    flash_tf32<<<dim3(NQ / 128, BATCH * NH), 256, FLASH_SMEM>>>(pQ, pK, pV, pAO);

    // 4) output projection
    GemmJobs oj;
    oj.j[0] = { pAO, pWo, bo, out, NQ, 3, (BATCH * NQ) / 128 };
    oj.j[1] = oj.j[0];
    oj.j[2] = oj.j[0];
    gemm_tf32<<<dim3(8, 32, 1), 256, GEMM_SMEM>>>(oj, pc, ps);
}

// round 15
// speedup vs baseline: 1.5109x; 1.5109x over previous
#include <cuda_runtime.h>
#include <math.h>
#include <stdint.h>

#define BATCH 2
#define NQ 2048
#define NKV 2112
#define CDIM 1024
#define NH 16
#define HD 64
#define NKEEP 2048
#define QW 64
#define SCALE 0.125f

// Scratch (device globals; allocation is forbidden)
__device__ float g_Qh[BATCH * NH * NQ * HD];
__device__ float g_Kh[BATCH * NH * NKV * HD];
__device__ float g_Vh[BATCH * NH * NKV * HD];
__device__ float g_AO[BATCH * NQ * CDIM];
__device__ float g_ct[NQ * 32];
__device__ float g_st[NQ * 32];

// ---------------------------------------------------------------------------
__device__ __forceinline__ float f2tf(float f) {
    uint32_t u;
    asm("cvt.rna.tf32.f32 %0, %1;" : "=r"(u) : "f"(f));
    return __uint_as_float(u);
}
__device__ __forceinline__ float4 f2tf4(float4 v) {
    return make_float4(f2tf(v.x), f2tf(v.y), f2tf(v.z), f2tf(v.w));
}

__device__ __forceinline__ void mma8(float c[4], float a0, float a1, float a2, float a3,
                                     float b0, float b1) {
    asm volatile(
        "mma.sync.aligned.m16n8k8.row.col.f32.tf32.tf32.f32 "
        "{%0,%1,%2,%3}, {%4,%5,%6,%7}, {%8,%9}, {%0,%1,%2,%3};\n"
        : "+f"(c[0]), "+f"(c[1]), "+f"(c[2]), "+f"(c[3])
        : "r"(__float_as_uint(a0)), "r"(__float_as_uint(a1)),
          "r"(__float_as_uint(a2)), "r"(__float_as_uint(a3)),
          "r"(__float_as_uint(b0)), "r"(__float_as_uint(b1)));
}

// ---------------------------------------------------------------------------
__global__ void rope_table_kernel(float* __restrict__ ct, float* __restrict__ st) {
    int idx = blockIdx.x * blockDim.x + threadIdx.x;
    if (idx >= NQ * 32) return;
    int n = idx >> 5;
    int p = idx & 31;
    int j = p & 15;
    float coord = (p < 16) ? (float)(n & (QW - 1)) : (float)(n / QW);
    float freq = powf(10000.0f, -(float)j / 16.0f);
    float ang = coord * freq;
    ct[idx] = cosf(ang);
    st[idx] = sinf(ang);
}

// ---------------------------------------------------------------------------
// tf32 GEMM (R6 structure): out = X(M x 1024) @ W(1024 x 1024) + bias.
// Block 128x128, BK=16, 256 threads (8 warps 4x2, warp tile 32x64).
// Double-buffered static smem + register prefetch; one __syncthreads per iter.
// mode: 0 V-scatter, 1 Q(+RoPE+scale), 2 K(+RoPE if n<NKEEP), 3 row-major.
// blockIdx.z selects the job (merged Q/K/V launch).
// ---------------------------------------------------------------------------
#define BK 16
#define A_STR 20
#define B_STR 136
#define NK_IT 64

struct GemmJob {
    const float* A;
    const float* W;
    const float* bias;
    float* out;
    int Ntok;
    int mode;
    int yblocks;
};
struct GemmJobs { GemmJob j[3]; };

__global__ __launch_bounds__(256, 2)
void gemm_tf32(GemmJobs jobs, const float* __restrict__ ct, const float* __restrict__ st) {
    const GemmJob jb = jobs.j[blockIdx.z];
    if ((int)blockIdx.y >= jb.yblocks) return;

    __shared__ float As[2][128 * A_STR];
    __shared__ float Bs[2][BK * B_STR];

    int tid = threadIdx.x;
    int lane = tid & 31, wid = tid >> 5;
    int wm = wid >> 1, wn = wid & 1;
    int g = lane >> 2, q4 = lane & 3;
    int row0 = blockIdx.y * 128, col0 = blockIdx.x * 128;

    int ar = tid >> 1, ac = (tid & 1) << 3;
    int br = tid >> 4, bc = (tid & 15) << 3;

    const float* Ap = jb.A + (size_t)(row0 + ar) * 1024 + ac;
    const float* Wp = jb.W + (size_t)br * 1024 + col0 + bc;

    float acc[2][8][4];
#pragma unroll
    for (int mi = 0; mi < 2; mi++)
#pragma unroll
        for (int ni = 0; ni < 8; ni++)
#pragma unroll
            for (int j = 0; j < 4; j++) acc[mi][ni][j] = 0.0f;

    // prologue: stage tile 0
    {
        float4 a0 = *(const float4*)(Ap);
        float4 a1 = *(const float4*)(Ap + 4);
        float4 b0 = *(const float4*)(Wp);
        float4 b1 = *(const float4*)(Wp + 4);
        *(float4*)&As[0][ar * A_STR + ac]     = f2tf4(a0);
        *(float4*)&As[0][ar * A_STR + ac + 4] = f2tf4(a1);
        *(float4*)&Bs[0][br * B_STR + bc]     = f2tf4(b0);
        *(float4*)&Bs[0][br * B_STR + bc + 4] = f2tf4(b1);
    }

    int cur = 0;
    for (int it = 1; it <= NK_IT; it++) {
        __syncthreads();

        float4 na0, na1, nb0, nb1;
        if (it < NK_IT) {
            na0 = *(const float4*)(Ap + it * BK);
            na1 = *(const float4*)(Ap + it * BK + 4);
            nb0 = *(const float4*)(Wp + (size_t)it * BK * 1024);
            nb1 = *(const float4*)(Wp + (size_t)it * BK * 1024 + 4);
        }

        const float* Ac = As[cur];
        const float* Bc = Bs[cur];
#pragma unroll
        for (int kc = 0; kc < BK; kc += 8) {
            float a[2][4], b[8][2];
#pragma unroll
            for (int mi = 0; mi < 2; mi++) {
                int m = wm * 32 + mi * 16;
                a[mi][0] = Ac[(m + g) * A_STR + kc + q4];
                a[mi][1] = Ac[(m + 8 + g) * A_STR + kc + q4];
                a[mi][2] = Ac[(m + g) * A_STR + kc + 4 + q4];
                a[mi][3] = Ac[(m + 8 + g) * A_STR + kc + 4 + q4];
            }
#pragma unroll
            for (int ni = 0; ni < 8; ni++) {
                int n = wn * 64 + ni * 8 + g;
                b[ni][0] = Bc[(kc + q4) * B_STR + n];
                b[ni][1] = Bc[(kc + 4 + q4) * B_STR + n];
            }
#pragma unroll
            for (int mi = 0; mi < 2; mi++)
#pragma unroll
                for (int ni = 0; ni < 8; ni++)
                    mma8(acc[mi][ni], a[mi][0], a[mi][1], a[mi][2], a[mi][3],
                         b[ni][0], b[ni][1]);
        }

        if (it < NK_IT) {
            int nxt = cur ^ 1;
            *(float4*)&As[nxt][ar * A_STR + ac]     = f2tf4(na0);
            *(float4*)&As[nxt][ar * A_STR + ac + 4] = f2tf4(na1);
            *(float4*)&Bs[nxt][br * B_STR + bc]     = f2tf4(nb0);
            *(float4*)&Bs[nxt][br * B_STR + bc + 4] = f2tf4(nb1);
        }
        cur ^= 1;
    }

    // epilogue
    int Ntok = jb.Ntok, mode = jb.mode;
#pragma unroll
    for (int mi = 0; mi < 2; mi++) {
#pragma unroll
        for (int ri = 0; ri < 2; ri++) {
            int gr = row0 + wm * 32 + mi * 16 + ri * 8 + g;
            int b = 0, n = gr;
            if (mode != 3) { b = gr / Ntok; n = gr - b * Ntok; }
            bool dorope = (mode == 1) || (mode == 2 && n < NKEEP);
#pragma unroll
            for (int ni = 0; ni < 8; ni++) {
                int gc = col0 + wn * 64 + ni * 8 + 2 * q4;
                float v0 = acc[mi][ni][ri * 2 + 0] + jb.bias[gc];
                float v1 = acc[mi][ni][ri * 2 + 1] + jb.bias[gc + 1];
                if (mode == 3) {
                    *(float2*)(jb.out + (size_t)gr * 1024 + gc) = make_float2(v0, v1);
                } else {
                    if (dorope) {
                        int p = (gc & 63) >> 1;
                        float cs = ct[n * 32 + p];
                        float sn = st[n * 32 + p];
                        float e = v0, o = v1;
                        v0 = e * cs - o * sn;
                        v1 = e * sn + o * cs;
                    }
                    if (mode == 1) { v0 *= SCALE; v1 *= SCALE; }
                    int h = (gc >> 6) & 15;
                    float* dst = jb.out + (((size_t)(b * NH + h) * Ntok + n) * HD + (gc & 63));
                    *(float2*)dst = make_float2(v0, v1);
                }
            }
        }
    }
}

// ---------------------------------------------------------------------------
// tf32 flash attention (R9 structure): block = one (b,h), 128 q rows;
// 8 warps x 16 rows; Bc=32; double-buffered K/V + register prefetch;
// 1 syncthreads per tile; 2 CTAs/SM. Q is pre-scaled by the projection GEMM.
// ---------------------------------------------------------------------------
#define QS_S 68
#define KS_S 68
#define VS_S 72
#define PS_S 36
#define BC 32
#define NTILE (NKV / BC)
#define FLASH_SMEM ((128 * QS_S + 2 * BC * KS_S + 2 * BC * VS_S + 128 * PS_S) * 4)

__global__ __launch_bounds__(256, 2)
void flash_tf32(const float* __restrict__ Qh, const float* __restrict__ Kh,
                const float* __restrict__ Vh, float* __restrict__ Out) {
    extern __shared__ float sm[];
    float* Qs = sm;                                    // [128][68]
    float* Ks0 = Qs + 128 * QS_S;                      // [2][32][68]
    float* Vs0 = Ks0 + 2 * BC * KS_S;                  // [2][32][72]
    float* Ps = Vs0 + 2 * BC * VS_S;                   // [128][36]

    int tid = threadIdx.x, lane = tid & 31, wid = tid >> 5;
    int g = lane >> 2, q4 = lane & 3;
    int bh = blockIdx.y, qt = blockIdx.x;
    int r0 = wid * 16;

    const float* Qb = Qh + ((size_t)bh * NQ + qt * 128) * HD;
    const float* Kb = Kh + (size_t)bh * NKV * HD;
    const float* Vb = Vh + (size_t)bh * NKV * HD;

    int sr[2], sdg[2];
#pragma unroll
    for (int t = 0; t < 2; t++) {
        int idx = tid + t * 256;
        sr[t] = idx >> 4;
        sdg[t] = (idx & 15) << 2;
    }

    // stage Q (already scaled; tf32-round)
#pragma unroll
    for (int t = 0; t < 8; t++) {
        int idx = tid + t * 256;
        int r = idx >> 4, dg = (idx & 15) << 2;
        float4 v = *(const float4*)(Qb + r * 64 + dg);
        *(float4*)&Qs[r * QS_S + dg] = f2tf4(v);
    }

    // stage K/V tile 0 into buffer 0
#pragma unroll
    for (int t = 0; t < 2; t++) {
        float4 kv = *(const float4*)(Kb + sr[t] * 64 + sdg[t]);
        float4 vv = *(const float4*)(Vb + sr[t] * 64 + sdg[t]);
        *(float4*)&Ks0[sr[t] * KS_S + sdg[t]] = f2tf4(kv);
        *(float4*)&Vs0[sr[t] * VS_S + sdg[t]] = f2tf4(vv);
    }

    float m0 = -INFINITY, m1 = -INFINITY, l0 = 0.0f, l1 = 0.0f;
    float o[8][4];
#pragma unroll
    for (int ni = 0; ni < 8; ni++)
#pragma unroll
        for (int j = 0; j < 4; j++) o[ni][j] = 0.0f;

    int cur = 0;
    for (int kt = 0; kt < NTILE; kt++) {
        __syncthreads();

        float4 pk[2], pv[2];
        if (kt + 1 < NTILE) {
            const float* Kn = Kb + (size_t)(kt + 1) * BC * 64;
            const float* Vn = Vb + (size_t)(kt + 1) * BC * 64;
#pragma unroll
            for (int t = 0; t < 2; t++) {
                pk[t] = *(const float4*)(Kn + sr[t] * 64 + sdg[t]);
                pv[t] = *(const float4*)(Vn + sr[t] * 64 + sdg[t]);
            }
        }

        const float* Ksc = Ks0 + cur * BC * KS_S;
        const float* Vsc = Vs0 + cur * BC * VS_S;

        // S = Q @ K^T  (16 x 32 per warp)
        float s[4][4];
#pragma unroll
        for (int ni = 0; ni < 4; ni++)
#pragma unroll
            for (int j = 0; j < 4; j++) s[ni][j] = 0.0f;

#pragma unroll
        for (int kc = 0; kc < 64; kc += 8) {
            float a0 = Qs[(r0 + g) * QS_S + kc + q4];
            float a1 = Qs[(r0 + 8 + g) * QS_S + kc + q4];
            float a2 = Qs[(r0 + g) * QS_S + kc + 4 + q4];
            float a3 = Qs[(r0 + 8 + g) * QS_S + kc + 4 + q4];
#pragma unroll
            for (int ni = 0; ni < 4; ni++) {
                float b0 = Ksc[(ni * 8 + g) * KS_S + kc + q4];
                float b1 = Ksc[(ni * 8 + g) * KS_S + kc + 4 + q4];
                mma8(s[ni], a0, a1, a2, a3, b0, b1);
            }
        }

        // online softmax
        float mt0 = -INFINITY, mt1 = -INFINITY;
#pragma unroll
        for (int ni = 0; ni < 4; ni++) {
            mt0 = fmaxf(mt0, fmaxf(s[ni][0], s[ni][1]));
            mt1 = fmaxf(mt1, fmaxf(s[ni][2], s[ni][3]));
        }
        mt0 = fmaxf(mt0, __shfl_xor_sync(0xffffffffu, mt0, 1));
        mt0 = fmaxf(mt0, __shfl_xor_sync(0xffffffffu, mt0, 2));
        mt1 = fmaxf(mt1, __shfl_xor_sync(0xffffffffu, mt1, 1));
        mt1 = fmaxf(mt1, __shfl_xor_sync(0xffffffffu, mt1, 2));
        float mn0 = fmaxf(m0, mt0), mn1 = fmaxf(m1, mt1);
        float al0 = __expf(m0 - mn0), al1 = __expf(m1 - mn1);
        m0 = mn0; m1 = mn1;

        float sum0 = 0.0f, sum1 = 0.0f;
#pragma unroll
        for (int ni = 0; ni < 4; ni++) {
            s[ni][0] = __expf(s[ni][0] - mn0);
            s[ni][1] = __expf(s[ni][1] - mn0);
            s[ni][2] = __expf(s[ni][2] - mn1);
            s[ni][3] = __expf(s[ni][3] - mn1);
            sum0 += s[ni][0] + s[ni][1];
            sum1 += s[ni][2] + s[ni][3];
        }
        sum0 += __shfl_xor_sync(0xffffffffu, sum0, 1);
        sum0 += __shfl_xor_sync(0xffffffffu, sum0, 2);
        sum1 += __shfl_xor_sync(0xffffffffu, sum1, 1);
        sum1 += __shfl_xor_sync(0xffffffffu, sum1, 2);
        l0 = l0 * al0 + sum0;
        l1 = l1 * al1 + sum1;
#pragma unroll
        for (int ni = 0; ni < 8; ni++) {
            o[ni][0] *= al0; o[ni][1] *= al0;
            o[ni][2] *= al1; o[ni][3] *= al1;
        }

        // P (warp-private rows), tf32
#pragma unroll
        for (int ni = 0; ni < 4; ni++) {
            int c = ni * 8 + 2 * q4;
            *(float2*)&Ps[(r0 + g) * PS_S + c] =
                make_float2(f2tf(s[ni][0]), f2tf(s[ni][1]));
            *(float2*)&Ps[(r0 + 8 + g) * PS_S + c] =
                make_float2(f2tf(s[ni][2]), f2tf(s[ni][3]));
        }
        __syncwarp();

        // O += P @ V
#pragma unroll
        for (int kc = 0; kc < BC; kc += 8) {
            float a0 = Ps[(r0 + g) * PS_S + kc + q4];
            float a1 = Ps[(r0 + 8 + g) * PS_S + kc + q4];
            float a2 = Ps[(r0 + g) * PS_S + kc + 4 + q4];
            float a3 = Ps[(r0 + 8 + g) * PS_S + kc + 4 + q4];
#pragma unroll
            for (int ni = 0; ni < 8; ni++) {
                float b0 = Vsc[(kc + q4) * VS_S + ni * 8 + g];
                float b1 = Vsc[(kc + 4 + q4) * VS_S + ni * 8 + g];
                mma8(o[ni], a0, a1, a2, a3, b0, b1);
            }
        }

        if (kt + 1 < NTILE) {
            int nxt = cur ^ 1;
            float* Kn = Ks0 + nxt * BC * KS_S;
            float* Vn = Vs0 + nxt * BC * VS_S;
#pragma unroll
            for (int t = 0; t < 2; t++) {
                *(float4*)&Kn[sr[t] * KS_S + sdg[t]] = f2tf4(pk[t]);
                *(float4*)&Vn[sr[t] * VS_S + sdg[t]] = f2tf4(pv[t]);
            }
        }
        cur ^= 1;
    }

    // epilogue
    float inv0 = 1.0f / l0, inv1 = 1.0f / l1;
    int b = bh >> 4, h = bh & 15;
    int nr = qt * 128 + r0 + g;
    size_t base0 = ((size_t)(b * NQ + nr)) * CDIM + h * 64;
    size_t base1 = base0 + (size_t)8 * CDIM;
#pragma unroll
    for (int ni = 0; ni < 8; ni++) {
        int c = ni * 8 + 2 * q4;
        *(float2*)(Out + base0 + c) = make_float2(o[ni][0] * inv0, o[ni][1] * inv0);
        *(float2*)(Out + base1 + c) = make_float2(o[ni][2] * inv1, o[ni][3] * inv1);
    }
}

// ---------------------------------------------------------------------------
extern "C" void kernel_launch(void* const* d_in, const int* in_sizes, int n_in,
                              void* d_out, int out_size) {
    const float* q  = (const float*)d_in[0];
    const float* k  = (const float*)d_in[1];
    const float* v  = (const float*)d_in[2];
    const float* Wq = (const float*)d_in[3];
    const float* bq = (const float*)d_in[4];
    const float* Wk = (const float*)d_in[5];
    const float* bk = (const float*)d_in[6];
    const float* Wv = (const float*)d_in[7];
    const float* bv = (const float*)d_in[8];
    const float* Wo = (const float*)d_in[9];
    const float* bo = (const float*)d_in[10];
    float* out = (float*)d_out;

    float *pQ, *pK, *pV, *pAO, *pc, *ps;
    cudaGetSymbolAddress((void**)&pQ,  g_Qh);
    cudaGetSymbolAddress((void**)&pK,  g_Kh);
    cudaGetSymbolAddress((void**)&pV,  g_Vh);
    cudaGetSymbolAddress((void**)&pAO, g_AO);
    cudaGetSymbolAddress((void**)&pc,  g_ct);
    cudaGetSymbolAddress((void**)&ps,  g_st);

    cudaFuncSetAttribute(flash_tf32, cudaFuncAttributeMaxDynamicSharedMemorySize,
                         FLASH_SMEM);

    rope_table_kernel<<<(NQ * 32 + 255) / 256, 256>>>(pc, ps);

    // merged Q/K/V projection GEMMs (z = job)
    GemmJobs pj;
    pj.j[0] = { q, Wq, bq, pQ, NQ,  1, (BATCH * NQ)  / 128 };  // 32
    pj.j[1] = { k, Wk, bk, pK, NKV, 2, (BATCH * NKV) / 128 };  // 33
    pj.j[2] = { v, Wv, bv, pV, NKV, 0, (BATCH * NKV) / 128 };  // 33
    gemm_tf32<<<dim3(8, 33, 3), 256>>>(pj, pc, ps);

    // attention
    flash_tf32<<<dim3(NQ / 128, BATCH * NH), 256, FLASH_SMEM>>>(pQ, pK, pV, pAO);

    // output projection
    GemmJobs oj;
    oj.j[0] = { pAO, Wo, bo, out, NQ, 3, (BATCH * NQ) / 128 };
    oj.j[1] = oj.j[0];
    oj.j[2] = oj.j[0];
    gemm_tf32<<<dim3(8, 32, 1), 256>>>(oj, pc, ps);
}